// round 17
// baseline (speedup 1.0000x reference)
#include <cuda_runtime.h>
#include <cuda_fp16.h>
#include <math.h>
#include <stdint.h>

// Problem constants
#define Bq   8
#define Nn   8192
#define Hh   256
#define Ff   320
#define Ss   32
#define Mtot (Bq * Nn)      // 65536
#define NSPLIT 64

// Scratch (static device globals — no cudaMalloc allowed)
__device__ __half g_xh[(size_t)Mtot * Hh];         // gated features fp16 [B*N, H]
__device__ float g_np[2 * Mtot];                   // partial norm^2 (nt 0/1)
__device__ float g_nrm[Mtot];                      // combined L2 norm
__device__ float g_part[(size_t)NSPLIT * Bq * Ss * Hh];  // split-K partials
__device__ __half g_wq[(size_t)Bq * Ss * Nn];      // fp16 softmax weights (pool operand)
// combined weights [Wi;Wj] = 512 rows x 320 cols, fp16,
// tiled as [kchunk 10][n 512][k 32] for direct cp.async
__device__ __half g_w[512 * Ff];

// ======================= helpers ============================================
__device__ __forceinline__ uint32_t smem_u32(const void* p) {
    uint32_t a;
    asm("{ .reg .u64 t; cvta.to.shared.u64 t, %1; cvt.u32.u64 %0, t; }"
        : "=r"(a) : "l"(p));
    return a;
}
// SW128 swizzle for 128B rows: bits[6:4] ^= bits[9:7]
__device__ __forceinline__ uint32_t swz128(uint32_t o) {
    return o ^ ((o >> 3) & 0x70);
}
// swizzle for 512B rows: 16B-chunk index ^= row&7
__device__ __forceinline__ uint32_t swzx(uint32_t o) {
    return o ^ (((o >> 9) & 7) << 4);
}
__device__ __forceinline__ void cp16(uint32_t dst, const void* src) {
    asm volatile("cp.async.cg.shared.global [%0], [%1], 16;"
                 :: "r"(dst), "l"(src) : "memory");
}
#define CP_COMMIT() asm volatile("cp.async.commit_group;" ::: "memory")
#define CP_WAIT(n)  asm volatile("cp.async.wait_group %0;" :: "n"(n) : "memory")

#define LDSM4(r, addr)                                                         \
    asm volatile("ldmatrix.sync.aligned.m8n8.x4.shared.b16 {%0,%1,%2,%3}, [%4];" \
                 : "=r"((r)[0]), "=r"((r)[1]), "=r"((r)[2]), "=r"((r)[3])      \
                 : "r"(addr))
#define LDSM4T(r, addr)                                                        \
    asm volatile("ldmatrix.sync.aligned.m8n8.x4.trans.shared.b16 {%0,%1,%2,%3}, [%4];" \
                 : "=r"((r)[0]), "=r"((r)[1]), "=r"((r)[2]), "=r"((r)[3])      \
                 : "r"(addr))

__device__ __forceinline__ void mma16816h(float* d, const uint32_t* a,
                                          uint32_t b0, uint32_t b1) {
    asm volatile(
        "mma.sync.aligned.m16n8k16.row.col.f32.f16.f16.f32 "
        "{%0,%1,%2,%3}, {%4,%5,%6,%7}, {%8,%9}, {%0,%1,%2,%3};"
        : "+f"(d[0]), "+f"(d[1]), "+f"(d[2]), "+f"(d[3])
        : "r"(a[0]), "r"(a[1]), "r"(a[2]), "r"(a[3]), "r"(b0), "r"(b1));
}

// fast gate via MUFU.TANH: sigmoid(zi)*tanh(zj), sigmoid(z)=0.5*(1+tanh(z/2))
__device__ __forceinline__ float gate_fn(float zi, float zj) {
    float si, tj;
    asm("tanh.approx.f32 %0, %1;" : "=f"(si) : "f"(0.5f * zi));
    asm("tanh.approx.f32 %0, %1;" : "=f"(tj) : "f"(zj));
    return (0.5f + 0.5f * si) * tj;
}

// GEMM SMEM map (dynamic):
//  2 stages of 49152B: A fp16 +0 (16KB, 128 rows x 128B), B fp16 +16384 (32KB)
//  nbuf (256 f32) at 98304; bias (256 f32) at 99328
#define STG     49152
#define SM_NB   98304
#define SM_BIAS 99328
#define SM_TOT  100352

// ============================================================================
// k_wconv: convert+tile weights: g_w[(c*512+n)*32+kk], f = c*32+kk
// ============================================================================
__global__ __launch_bounds__(256) void k_wconv(const float* __restrict__ Wi,
                                               const float* __restrict__ Wj) {
    int i = blockIdx.x * 256 + threadIdx.x;   // 0..163839
    int c  = i >> 14;
    int r  = i & 16383;
    int n  = r >> 5;
    int kk = r & 31;
    int f  = c * 32 + kk;
    float v = (n < 256) ? Wi[n * Ff + f] : Wj[(n - 256) * Ff + f];
    g_w[i] = __float2half_rn(v);
}

// ============================================================================
// k_gemm_mma: dual GEMM (fp16 HMMA) + in-register gate + partial norm.
// CTA: 128M x 256N, K chunks of 64 (5 iterations). B rows interleaved:
// local row r: q=r>>4, rr=r&15; global n = (q&1)*256 + nt*128 + (q>>1)*16+rr.
// 512 thr = 16 warps; warp (wm=wid>>1, wn=wid&1): tile 16m x 128n.
// ============================================================================
__global__ __launch_bounds__(512, 1) void k_gemm_mma(
    const float* __restrict__ x,
    const float* __restrict__ bi, const float* __restrict__ bj)
{
    extern __shared__ __align__(128) char smem[];
    const uint32_t sb = smem_u32(smem);
    const int t    = threadIdx.x;
    const int lane = t & 31;
    const int wid  = t >> 5;
    const int wm   = wid >> 1;            // 0..7
    const int wn   = wid & 1;             // 0..1
    const int m0   = blockIdx.x * 128;
    const int nt   = blockIdx.y;          // 0/1: which 128-col slice of Di/Dj

    // bias preload: biasS[0..127]=bi slice, [128..255]=bj slice
    float* biasS = (float*)(smem + SM_BIAS);
    if (t < 128)            biasS[t] = bi[nt * 128 + t];
    else if (t < 256)       biasS[t] = bj[nt * 128 + (t - 128)];

    float acc[16][4] = {};

    // A addressing: thread owns row t>>2, 16 floats at col (t&3)*16
    const int xrow = t >> 2, xc = t & 3;
    const float* xptr = x + (size_t)(m0 + xrow) * Ff + xc * 16;

    // ---- B issue into stage st for chunk it (256 rows x 128B fp16, interleaved)
    auto issueB = [&](int it, int st) {
        uint32_t bB = sb + st * STG + 16384;
#pragma unroll
        for (int i = 0; i < 4; i++) {
            int e    = t + i * 512;        // 0..2047
            int brow = e >> 3;             // local row 0..255
            int kc   = e & 7;              // 16B chunk within 128B row
            int kh   = kc >> 2;            // which g_w k32 sub-chunk
            int kcl  = kc & 3;
            int q    = brow >> 4;
            int rr   = brow & 15;
            int gn   = (q & 1) * 256 + nt * 128 + (q >> 1) * 16 + rr;
            uint32_t so = swz128((uint32_t)brow * 128 + kc * 16);
            cp16(bB + so,
                 g_w + (size_t)(2 * it + kh) * 16384 + (size_t)gn * 32 + kcl * 8);
        }
    };
    // ---- A convert fp32 -> fp16 (16 vals/thread), STS swizzled
    auto stsA = [&](const float4* v, int st) {
        uint32_t pv[8];
#pragma unroll
        for (int q = 0; q < 4; q++) {
            __half2 h0 = __floats2half2_rn(v[q].x, v[q].y);
            __half2 h1 = __floats2half2_rn(v[q].z, v[q].w);
            pv[2 * q]     = *(uint32_t*)&h0;
            pv[2 * q + 1] = *(uint32_t*)&h1;
        }
        uint32_t off = swz128((uint32_t)xrow * 128 + xc * 32);
        *(uint4*)(smem + st * STG + off) =
            make_uint4(pv[0], pv[1], pv[2], pv[3]);
        *(uint4*)(smem + st * STG + (off ^ 16)) =
            make_uint4(pv[4], pv[5], pv[6], pv[7]);
    };
    // ---- compute one k64 chunk from stage st
    auto compute = [&](int st) {
        uint32_t aB = sb + st * STG;
        uint32_t bB = aB + 16384;
        const uint32_t arow = wm * 16 + (lane & 7) + ((lane >> 3) & 1) * 8;
        const uint32_t c16  = (lane >> 4) & 1;
        const uint32_t brow = wn * 128 + (lane & 7) + ((lane >> 3) & 1) * 8;
#pragma unroll
        for (int k16 = 0; k16 < 4; k16++) {
            uint32_t ao = swz128(arow * 128 + k16 * 32 + c16 * 16);
            uint32_t a4[4];
            LDSM4(a4, aB + ao);
#pragma unroll
            for (int bn = 0; bn < 8; bn++) {
                uint32_t bo = swz128((brow + bn * 16) * 128 + k16 * 32 + c16 * 16);
                uint32_t b4[4];
                LDSM4(b4, bB + bo);
                mma16816h(acc[bn * 2],     a4, b4[0], b4[2]);
                mma16816h(acc[bn * 2 + 1], a4, b4[1], b4[3]);
            }
        }
    };

    // ---- prologue: chunk 0 into buf 0
    {
        float4 v[4];
#pragma unroll
        for (int q = 0; q < 4; q++) v[q] = *(const float4*)(xptr + q * 4);
        stsA(v, 0);
    }
    issueB(0, 0);
    CP_COMMIT();

    // ---- main loop: 5 k64 chunks, double buffered
    for (int it = 0; it < 5; it++) {
        int buf = it & 1;
        CP_WAIT(0);
        __syncthreads();
        float4 xn[4];
        if (it < 4) {
#pragma unroll
            for (int q = 0; q < 4; q++)
                xn[q] = *(const float4*)(xptr + (it + 1) * 64 + q * 4);
            issueB(it + 1, buf ^ 1);
            CP_COMMIT();
        }
        compute(buf);
        if (it < 4) stsA(xn, buf ^ 1);
    }

    // ---- in-register epilogue: gate + STG fp16 + norm
    // bn=2e (Di) / bn=2e+1 (Dj) share h-block hbl = wn*4+e.
    const int r0 = m0 + wm * 16 + (lane >> 2);
    const int c2 = (lane & 3) * 2;
    float nrm0 = 0.0f, nrm1 = 0.0f;
#pragma unroll
    for (int e = 0; e < 4; e++) {
        int hbl = wn * 4 + e;
#pragma unroll
        for (int hf = 0; hf < 2; hf++) {
            int hl = hbl * 16 + hf * 8 + c2;        // local col 0..127
            float2 bi2 = *(float2*)&biasS[hl];
            float2 bj2 = *(float2*)&biasS[128 + hl];
            float* aD = acc[4 * e + hf];
            float* aJ = acc[4 * e + 2 + hf];
            float o00 = gate_fn(aD[0] + bi2.x, aJ[0] + bj2.x);
            float o01 = gate_fn(aD[1] + bi2.y, aJ[1] + bj2.y);
            float o10 = gate_fn(aD[2] + bi2.x, aJ[2] + bj2.x);
            float o11 = gate_fn(aD[3] + bi2.y, aJ[3] + bj2.y);
            nrm0 += o00 * o00 + o01 * o01;
            nrm1 += o10 * o10 + o11 * o11;
            __half2 p0 = __floats2half2_rn(o00, o01);
            __half2 p1 = __floats2half2_rn(o10, o11);
            int hg = nt * 128 + hl;
            *(uint32_t*)&g_xh[(size_t)r0 * Hh + hg]       = *(uint32_t*)&p0;
            *(uint32_t*)&g_xh[(size_t)(r0 + 8) * Hh + hg] = *(uint32_t*)&p1;
        }
    }
    nrm0 += __shfl_xor_sync(0xFFFFFFFFu, nrm0, 1);
    nrm0 += __shfl_xor_sync(0xFFFFFFFFu, nrm0, 2);
    nrm1 += __shfl_xor_sync(0xFFFFFFFFu, nrm1, 1);
    nrm1 += __shfl_xor_sync(0xFFFFFFFFu, nrm1, 2);
    float* nbuf = (float*)(smem + SM_NB);
    if ((lane & 3) == 0) {
        nbuf[wn * 128 + wm * 16 + (lane >> 2)]     = nrm0;
        nbuf[wn * 128 + wm * 16 + (lane >> 2) + 8] = nrm1;
    }
    __syncthreads();
    if (t < 128)
        g_np[(size_t)nt * Mtot + m0 + t] = nbuf[t] + nbuf[128 + t];
}

// ============================================================================
// k_norm: combine the two GEMM norm partials once (read by 32 softmax rows)
// ============================================================================
__global__ __launch_bounds__(256) void k_norm() {
    int i = blockIdx.x * 256 + threadIdx.x;
    g_nrm[i] = sqrtf(g_np[i] + g_np[(size_t)Mtot + i]);
}

// ============================================================================
// k_weight: masked softmax over nodes. One block per (b,s).
// Writes fp32 weight output AND fp16 copy for the HMMA pool.
// ============================================================================
__global__ __launch_bounds__(256) void k_weight(const float* __restrict__ node_map,
                                                float* __restrict__ wout) {
    __shared__ float e[Nn];
    __shared__ float red[256];
    int bs = blockIdx.x;
    int b  = bs >> 5;
    const float* nm  = node_map + (size_t)bs * Nn;
    const float* nrm = g_nrm + (size_t)b * Nn;
    int t = threadIdx.x;
    float part = 0.0f;
    for (int n = t; n < Nn; n += 256) {
        float v  = nm[n] * nrm[n];
        float ev = (v > 0.0f) ? __expf(v) : 0.0f;
        e[n] = ev;
        part += ev;
    }
    red[t] = part;
    __syncthreads();
#pragma unroll
    for (int o = 128; o > 0; o >>= 1) {
        if (t < o) red[t] += red[t + o];
        __syncthreads();
    }
    float sum = red[0];
    float inv = (sum > 0.0f) ? (1.0f / sum) : 0.0f;
    float* wrow = wout + (size_t)bs * Nn;
    __half* wqrow = g_wq + (size_t)bs * Nn;
    for (int n = t; n < Nn; n += 256) {
        float wv = e[n] * inv;
        wrow[n]  = wv;
        wqrow[n] = __float2half_rn(wv);
    }
}

// ============================================================================
// k_pool: HMMA pooled GEMM, split-K. D[s,h] = sum_n w[s,n] * xh[n,h].
// grid (64 chunks, 1, 8 b), 256 thr = 8 warps (wm=wid>>2 m16, wn=wid&3 n64).
// w tile [32 s][128 k] fp16 resident; xh streamed in 32-node tiles (3 bufs).
// xh rows are [node][h] -> ldmatrix.trans for the B operand.
// ============================================================================
__global__ __launch_bounds__(256, 1) void k_pool() {
    extern __shared__ __align__(128) char psm[];
    const uint32_t sb = smem_u32(psm);
    const int t    = threadIdx.x;
    const int lane = t & 31;
    const int wid  = t >> 5;
    const int wm   = wid >> 2;            // 0..1
    const int wn   = wid & 3;             // 0..3
    const int chunk = blockIdx.x;         // 0..63
    const int b     = blockIdx.z;         // 0..7
    const int nbase = chunk * 128;

    // ---- load w tile: 32 rows x 256B (fp16, swzx on 512B-row formula is
    // wrong for 256B rows; store w tile with 512B stride, half used)
#pragma unroll
    for (int i = 0; i < 2; i++) {
        int e  = t + i * 256;             // 0..511
        int s  = e >> 4;
        int kc = e & 15;
        cp16(sb + swzx((uint32_t)s * 512 + kc * 16),
             g_wq + (size_t)(b * Ss + s) * Nn + nbase + kc * 8);
    }
    // ---- xh tile streamer (32 nodes x 512B)
    auto issueX = [&](int kk, int st) {
        uint32_t xb = sb + 16384 + st * 16384;
#pragma unroll
        for (int i = 0; i < 4; i++) {
            int e  = t + i * 256;
            int nn = e >> 5;
            int kc = e & 31;
            cp16(xb + swzx((uint32_t)nn * 512 + kc * 16),
                 g_xh + (size_t)(b * Nn + nbase + kk * 32 + nn) * Hh + kc * 8);
        }
    };
    issueX(0, 0); CP_COMMIT();            // group: w + x0
    issueX(1, 1); CP_COMMIT();

    float acc[8][4] = {};

    for (int kk = 0; kk < 4; kk++) {
        if (kk < 3) CP_WAIT(1); else CP_WAIT(0);
        __syncthreads();
        if (kk < 2) { issueX(kk + 2, (kk + 2) % 3); CP_COMMIT(); }
        uint32_t xb = sb + 16384 + (kk % 3) * 16384;
#pragma unroll
        for (int k16 = 0; k16 < 2; k16++) {
            const int kr0 = k16 * 16;
            // A frag: w[s][k] row-major, m16k16 at (wm*16, kk*32+kr0)
            uint32_t a4[4];
            {
                uint32_t r  = wm * 16 + (lane & 15);
                uint32_t cb = (uint32_t)(kk * 32 + kr0) * 2 + ((lane >> 4) & 1) * 16;
                LDSM4(a4, sb + swzx(r * 512 + cb));
            }
            // B frags: xh[node][h], trans -> (b0,b1) n8 blk0, (b2,b3) n8 blk1
#pragma unroll
            for (int j = 0; j < 4; j++) {
                uint32_t r  = kr0 + (lane & 7) + ((lane >> 3) & 1) * 8;
                uint32_t cb = (uint32_t)(wn * 64 + j * 16) * 2 + ((lane >> 4) & 1) * 16;
                uint32_t b4[4];
                LDSM4T(b4, xb + swzx(r * 512 + cb));
                mma16816h(acc[2 * j],     a4, b4[0], b4[1]);
                mma16816h(acc[2 * j + 1], a4, b4[2], b4[3]);
            }
        }
    }

    // ---- write fp32 partials
    const int s0 = wm * 16 + (lane >> 2);
    const size_t base = (size_t)(chunk * Bq + b) * Ss * Hh;
#pragma unroll
    for (int j = 0; j < 4; j++) {
#pragma unroll
        for (int hf = 0; hf < 2; hf++) {
            int h = wn * 64 + j * 16 + hf * 8 + (lane & 3) * 2;
            float* a = acc[2 * j + hf];
            *(float2*)&g_part[base + (size_t)s0 * Hh + h]       = make_float2(a[0], a[1]);
            *(float2*)&g_part[base + (size_t)(s0 + 8) * Hh + h] = make_float2(a[2], a[3]);
        }
    }
}

// ============================================================================
// k_final: deterministic split-K reduce + tanh (precise tanhf on output)
// ============================================================================
__global__ __launch_bounds__(256) void k_final(float* __restrict__ out) {
    int g = blockIdx.x * blockDim.x + threadIdx.x;
    float s = 0.0f;
#pragma unroll
    for (int c = 0; c < NSPLIT; c++) s += g_part[(size_t)c * (Bq * Ss * Hh) + g];
    out[g] = tanhf(s);
}

// ============================================================================
extern "C" void kernel_launch(void* const* d_in, const int* in_sizes, int n_in,
                              void* d_out, int out_size) {
    const float* x        = (const float*)d_in[0];
    const float* node_map = (const float*)d_in[1];
    const float* Wi       = (const float*)d_in[2];
    const float* bi       = (const float*)d_in[3];
    const float* Wj       = (const float*)d_in[4];
    const float* bj       = (const float*)d_in[5];
    float* out  = (float*)d_out;
    float* wout = out + (size_t)Bq * Ss * Hh;

    cudaFuncSetAttribute(k_gemm_mma, cudaFuncAttributeMaxDynamicSharedMemorySize, SM_TOT);
    cudaFuncSetAttribute(k_pool, cudaFuncAttributeMaxDynamicSharedMemorySize, 65536);

    k_wconv<<<(512 * Ff) / 256, 256>>>(Wi, Wj);
    k_gemm_mma<<<dim3(Mtot / 128, 2), 512, SM_TOT>>>(x, bi, bj);
    k_norm<<<Mtot / 256, 256>>>();
    k_weight<<<Bq * Ss, 256>>>(node_map, wout);
    k_pool<<<dim3(NSPLIT, 1, Bq), 256, 65536>>>();
    k_final<<<(Bq * Ss * Hh) / 256, 256>>>(out);
}